// round 9
// baseline (speedup 1.0000x reference)
#include <cuda_runtime.h>
#include <cstdint>

// dist[m,n] = ||x_m||^2 + ||w_n||^2 - 2<x_m,w_n>
// x [M=262144, K=64] fp32, omega [N=256, K=64] fp32, out [M,256,1] fp32.
// TF32 mma.sync, persistent CTAs (R8 skeleton, 92.2us) + NEW: per-warp
// smem-transpose epilogue -> fully coalesced st.global.cs.v4 stores.
#define M_TILE 128
#define K_DIM  64
#define N_DIM  256
#define LDA    68      // padded float stride: conflict-free frag reads
#define LDB    68
#define LDS_T  68      // stage stride
#define NTHREADS 512
#define NTILES 2048
#define GRID_SMS 148   // sm_100a B200

// dynamic smem layout (in floats)
#define F_SB    0                        // 256*68 = 17408
#define F_SA    17408                    // 2 bufs x 128*68 = 17408
#define F_P2    34816                    // 256
#define F_X2    35072                    // 2 x 128 = 256
#define F_STAGE 35328                    // 16 warps x 16*68 = 17408
#define SMEM_FLOATS 52736
#define SMEM_BYTES  (SMEM_FLOATS * 4)    // 210944 (< 227KB cap)

// ---------------------------------------------------------------------------
__device__ __forceinline__ uint32_t f2tf32(float f) {
    uint32_t u;
    asm("cvt.rna.tf32.f32 %0, %1;" : "=r"(u) : "f"(f));
    return u;
}

__device__ __forceinline__ void mma_tf32(float* d, const uint32_t* a,
                                         uint32_t b0, uint32_t b1) {
    asm volatile(
        "mma.sync.aligned.m16n8k8.row.col.f32.tf32.tf32.f32 "
        "{%0,%1,%2,%3}, {%4,%5,%6,%7}, {%8,%9}, {%0,%1,%2,%3};"
        : "+f"(d[0]), "+f"(d[1]), "+f"(d[2]), "+f"(d[3])
        : "r"(a[0]), "r"(a[1]), "r"(a[2]), "r"(a[3]), "r"(b0), "r"(b1));
}

__device__ __forceinline__ void stg_cs_f4(float* p, float4 v) {
    asm volatile("st.global.cs.v4.f32 [%0], {%1, %2, %3, %4};"
                 :: "l"(p), "f"(v.x), "f"(v.y), "f"(v.z), "f"(v.w) : "memory");
}

__device__ __forceinline__ float red16(float s) {
    s += __shfl_xor_sync(0xffffffffu, s, 8);
    s += __shfl_xor_sync(0xffffffffu, s, 4);
    s += __shfl_xor_sync(0xffffffffu, s, 2);
    s += __shfl_xor_sync(0xffffffffu, s, 1);
    return s;
}

// ---------------------------------------------------------------------------
// Persistent CTA: loops over [128 x 256] output tiles.
// 16 warps as 4(m) x 4(n); warp tile 32m x 64n; K unrolled (8 steps of 8).
// ---------------------------------------------------------------------------
__global__ void __launch_bounds__(NTHREADS, 1)
dist_kernel(const float* __restrict__ x,
            const float* __restrict__ omega,
            float* __restrict__ out) {
    extern __shared__ float sm[];
    uint32_t* sBu = (uint32_t*)(sm + F_SB);
    float*    sp2 = sm + F_P2;
    float*    sx2 = sm + F_X2;          // [2][128]

    const int tid = threadIdx.x;
    const int row16 = tid >> 4;         // 0..31
    const int c4    = tid & 15;

    // ---- stage B once (omega -> smem tf32) + p2 via shuffle reduce ----
    {
        const float4* gw = (const float4*)omega;
#pragma unroll
        for (int j = 0; j < 8; j++) {
            int i = tid + NTHREADS * j;          // 0..4095 (256 rows * 16 quads)
            int n = i >> 4, cc = i & 15;
            float4 v = __ldg(gw + i);
            float ss = red16(v.x * v.x + v.y * v.y + v.z * v.z + v.w * v.w);
            if ((tid & 15) == 0) sp2[n] = ss;
            uint4 t;
            t.x = f2tf32(v.x); t.y = f2tf32(v.y);
            t.z = f2tf32(v.z); t.w = f2tf32(v.w);
            *(uint4*)&sBu[n * LDB + cc * 4] = t;
        }
    }

    // ---- warp tiling constants ----
    const int warp = tid >> 5;
    const int lane = tid & 31;
    const int wm = warp >> 2;
    const int wn = warp & 3;
    const int mbase = wm * 32;
    const int nbase = wn * 64;
    const int lr = lane >> 2;           // 0..7
    const int lc = lane & 3;            // 0..3
    const int lrow  = lane >> 4;        // 0..1  (transpose read row-within-pair)
    const int lcol4 = (lane & 15) * 4;  // 0..60 (transpose read col)
    float* stg = sm + F_STAGE + warp * (16 * LDS_T);

    const int grid = gridDim.x;
    const int bid  = blockIdx.x;

    // ---- prefetch first tile into registers ----
    float4 v[4];
    {
        const float4* gx = (const float4*)(x + (long long)bid * M_TILE * K_DIM);
#pragma unroll
        for (int j = 0; j < 4; j++) v[j] = __ldg(gx + tid + NTHREADS * j);
    }

    int k = 0;
    for (int t = bid; t < NTILES; t += grid, k++) {
        const int b = k & 1;
        uint32_t* sAu = (uint32_t*)(sm + F_SA) + b * (M_TILE * LDA);

        // ---- stage prefetched regs -> smem buf b (+ x2 shuffle reduce) ----
#pragma unroll
        for (int j = 0; j < 4; j++) {
            int row = row16 + 32 * j;
            float4 w = v[j];
            float ss = red16(w.x * w.x + w.y * w.y + w.z * w.z + w.w * w.w);
            if ((tid & 15) == 0) sx2[b * 128 + row] = ss;
            uint4 tv;
            tv.x = f2tf32(w.x); tv.y = f2tf32(w.y);
            tv.z = f2tf32(w.z); tv.w = f2tf32(w.w);
            *(uint4*)&sAu[row * LDA + c4 * 4] = tv;
        }
        __syncthreads();

        // ---- issue prefetch LDGs for next tile (hidden under MMA) ----
        const int tn = t + grid;
        if (tn < NTILES) {
            const float4* gx = (const float4*)(x + (long long)tn * M_TILE * K_DIM);
#pragma unroll
            for (int j = 0; j < 4; j++) v[j] = __ldg(gx + tid + NTHREADS * j);
        }

        // ---- MMA: K in 8 steps of 8, operands from smem ----
        float acc[2][8][4];
#pragma unroll
        for (int mt = 0; mt < 2; mt++)
#pragma unroll
            for (int nt = 0; nt < 8; nt++)
#pragma unroll
                for (int i = 0; i < 4; i++) acc[mt][nt][i] = 0.f;

#pragma unroll
        for (int ks = 0; ks < 8; ks++) {
            const int k0 = ks * 8;
            uint32_t a[2][4];
#pragma unroll
            for (int mt = 0; mt < 2; mt++) {
                const int r0 = mbase + mt * 16 + lr;
                a[mt][0] = sAu[r0 * LDA + k0 + lc];
                a[mt][1] = sAu[(r0 + 8) * LDA + k0 + lc];
                a[mt][2] = sAu[r0 * LDA + k0 + lc + 4];
                a[mt][3] = sAu[(r0 + 8) * LDA + k0 + lc + 4];
            }
#pragma unroll
            for (int nt = 0; nt < 8; nt++) {
                const int n = nbase + nt * 8 + lr;
                uint32_t b0 = sBu[n * LDB + k0 + lc];
                uint32_t b1 = sBu[n * LDB + k0 + lc + 4];
                mma_tf32(acc[0][nt], a[0], b0, b1);
                mma_tf32(acc[1][nt], a[1], b0, b1);
            }
        }

        // ---- epilogue: per-warp smem transpose -> coalesced v4 stores ----
        const long long m0 = (long long)t * M_TILE;
#pragma unroll
        for (int mt = 0; mt < 2; mt++) {
            const int r0 = mbase + mt * 16 + lr;       // absolute tile row
            const float xr0 = sx2[b * 128 + r0];
            const float xr1 = sx2[b * 128 + r0 + 8];
            // write final values into stage (rows local 0..15)
#pragma unroll
            for (int nt = 0; nt < 8; nt++) {
                const int col = nt * 8 + 2 * lc;
                const float p0 = sp2[nbase + col];
                const float p1 = sp2[nbase + col + 1];
                float2 v0, v1;
                v0.x = xr0 + p0 - 2.f * acc[mt][nt][0];
                v0.y = xr0 + p1 - 2.f * acc[mt][nt][1];
                v1.x = xr1 + p0 - 2.f * acc[mt][nt][2];
                v1.y = xr1 + p1 - 2.f * acc[mt][nt][3];
                *(float2*)&stg[lr * LDS_T + col]       = v0;
                *(float2*)&stg[(lr + 8) * LDS_T + col] = v1;
            }
            __syncwarp();
            // read row-major, store coalesced
            const long long mtop = m0 + mbase + mt * 16;
#pragma unroll
            for (int i = 0; i < 8; i++) {
                const int r = 2 * i + lrow;
                float4 vv = *(float4*)&stg[r * LDS_T + lcol4];
                stg_cs_f4(out + (mtop + r) * N_DIM + nbase + lcol4, vv);
            }
            __syncwarp();
        }
    }
}

// ---------------------------------------------------------------------------
extern "C" void kernel_launch(void* const* d_in, const int* in_sizes, int n_in,
                              void* d_out, int out_size) {
    const float* p0 = (const float*)d_in[0];
    const float* p1 = (const float*)d_in[1];
    // x is the big tensor (16777216 elems), omega is 16384.
    const float* x = p0, *omega = p1;
    if (n_in >= 2 && in_sizes[0] < in_sizes[1]) { x = p1; omega = p0; }

    (void)cudaFuncSetAttribute(dist_kernel,
                               cudaFuncAttributeMaxDynamicSharedMemorySize,
                               SMEM_BYTES);
    int grid = GRID_SMS < NTILES ? GRID_SMS : NTILES;
    dist_kernel<<<grid, NTHREADS, SMEM_BYTES>>>(x, omega, (float*)d_out);
}

// round 11
// speedup vs baseline: 1.2099x; 1.2099x over previous
#include <cuda_runtime.h>
#include <cstdint>

// dist[m,n] = ||x_m||^2 + ||w_n||^2 - 2<x_m,w_n>
// x [M=262144, K=64] fp32, omega [N=256, K=64] fp32, out [M,256,1] fp32.
// TF32 mma.sync, persistent CTAs (R8 skeleton, 92.2us). R10: per-tile CTA-wide
// __syncthreads replaced by per-row-group named barriers (4 warps, 128 thr):
// each group stages its own 32 A-rows -> 4 independent pipelines per CTA.
#define M_TILE 128
#define K_DIM  64
#define N_DIM  256
#define LDA    68      // padded float stride: bank=(4*row+col)%32 -> conflict-free
#define LDB    68
#define NTHREADS 512
#define NTILES 2048
#define GRID_SMS 148   // sm_100a B200

// dynamic smem layout (in floats)
#define F_SB   0                        // 256*68 = 17408
#define F_SA   17408                    // 2 bufs x 128*68 = 17408
#define F_P2   34816                    // 256
#define F_X2   35072                    // 2 x 128
#define SMEM_FLOATS 35328
#define SMEM_BYTES  (SMEM_FLOATS * 4)   // 141312

// ---------------------------------------------------------------------------
__device__ __forceinline__ uint32_t f2tf32(float f) {
    uint32_t u;
    asm("cvt.rna.tf32.f32 %0, %1;" : "=r"(u) : "f"(f));
    return u;
}

__device__ __forceinline__ void mma_tf32(float* d, const uint32_t* a,
                                         uint32_t b0, uint32_t b1) {
    asm volatile(
        "mma.sync.aligned.m16n8k8.row.col.f32.tf32.tf32.f32 "
        "{%0,%1,%2,%3}, {%4,%5,%6,%7}, {%8,%9}, {%0,%1,%2,%3};"
        : "+f"(d[0]), "+f"(d[1]), "+f"(d[2]), "+f"(d[3])
        : "r"(a[0]), "r"(a[1]), "r"(a[2]), "r"(a[3]), "r"(b0), "r"(b1));
}

__device__ __forceinline__ void stg_cs_f2(float* p, float x, float y) {
    asm volatile("st.global.cs.v2.f32 [%0], {%1, %2};"
                 :: "l"(p), "f"(x), "f"(y) : "memory");
}

__device__ __forceinline__ float red16(float s) {
    s += __shfl_xor_sync(0xffffffffu, s, 8);
    s += __shfl_xor_sync(0xffffffffu, s, 4);
    s += __shfl_xor_sync(0xffffffffu, s, 2);
    s += __shfl_xor_sync(0xffffffffu, s, 1);
    return s;
}

// named barrier over 128 threads (ids 1..4; 0 reserved for __syncthreads)
__device__ __forceinline__ void group_bar(int id) {
    asm volatile("bar.sync %0, %1;" :: "r"(id), "r"(128) : "memory");
}

// ---------------------------------------------------------------------------
// Persistent CTA: loops over [128 x 256] output tiles.
// 16 warps as 4(m) x 4(n). Row group g = warps 4g..4g+3 (tids 128g..128g+127)
// owns A rows [32g, 32g+32) and syncs only among itself per tile.
// ---------------------------------------------------------------------------
__global__ void __launch_bounds__(NTHREADS, 1)
dist_kernel(const float* __restrict__ x,
            const float* __restrict__ omega,
            float* __restrict__ out) {
    extern __shared__ float sm[];
    uint32_t* sBu = (uint32_t*)(sm + F_SB);
    float*    sp2 = sm + F_P2;
    float*    sx2 = sm + F_X2;          // [2][128]

    const int tid = threadIdx.x;

    // ---- stage B once (omega -> smem tf32) + p2 via shuffle reduce ----
    {
        const float4* gw = (const float4*)omega;
#pragma unroll
        for (int j = 0; j < 8; j++) {
            int i = tid + NTHREADS * j;          // 0..4095 (256 rows * 16 quads)
            int n = i >> 4, cc = i & 15;
            float4 v = __ldg(gw + i);
            float ss = red16(v.x * v.x + v.y * v.y + v.z * v.z + v.w * v.w);
            if ((tid & 15) == 0) sp2[n] = ss;
            uint4 t;
            t.x = f2tf32(v.x); t.y = f2tf32(v.y);
            t.z = f2tf32(v.z); t.w = f2tf32(v.w);
            *(uint4*)&sBu[n * LDB + cc * 4] = t;
        }
    }
    __syncthreads();   // B + p2 visible to all groups before independent loops

    // ---- warp tiling constants ----
    const int warp = tid >> 5;
    const int lane = tid & 31;
    const int wm = warp >> 2;           // row group g (== tid>>7)
    const int wn = warp & 3;
    const int mbase = wm * 32;
    const int nbase = wn * 64;
    const int lr = lane >> 2;
    const int lc = lane & 3;
    const int local = tid & 127;        // thread index within row group

    const int grid = gridDim.x;
    const int bid  = blockIdx.x;

    // ---- prefetch first tile (group's own 32 rows: 512 float4 / 128 thr) ----
    float4 v[4];
    {
        const float4* gx = (const float4*)(x + (long long)bid * M_TILE * K_DIM)
                         + mbase * (K_DIM / 4);   // group row base
#pragma unroll
        for (int j = 0; j < 4; j++) v[j] = __ldg(gx + local + 128 * j);
    }

    int k = 0;
    for (int t = bid; t < NTILES; t += grid, k++) {
        const int b = k & 1;
        uint32_t* sAu = (uint32_t*)(sm + F_SA) + b * (M_TILE * LDA);

        // ---- stage prefetched regs -> smem buf b (group rows only) ----
#pragma unroll
        for (int j = 0; j < 4; j++) {
            int idx = local + 128 * j;           // 0..511
            int row = mbase + (idx >> 4);        // group row
            int quad = idx & 15;
            float4 w = v[j];
            float ss = red16(w.x * w.x + w.y * w.y + w.z * w.z + w.w * w.w);
            if ((idx & 15) == 0) sx2[b * 128 + row] = ss;
            uint4 tv;
            tv.x = f2tf32(w.x); tv.y = f2tf32(w.y);
            tv.z = f2tf32(w.z); tv.w = f2tf32(w.w);
            *(uint4*)&sAu[row * LDA + quad * 4] = tv;
        }
        group_bar(wm + 1);

        // ---- issue prefetch LDGs for next tile (hidden under MMA) ----
        const int tn = t + grid;
        if (tn < NTILES) {
            const float4* gx = (const float4*)(x + (long long)tn * M_TILE * K_DIM)
                             + mbase * (K_DIM / 4);
#pragma unroll
            for (int j = 0; j < 4; j++) v[j] = __ldg(gx + local + 128 * j);
        }

        // ---- MMA: K in 8 steps of 8, operands from smem ----
        float acc[2][8][4];
#pragma unroll
        for (int mt = 0; mt < 2; mt++)
#pragma unroll
            for (int nt = 0; nt < 8; nt++)
#pragma unroll
                for (int i = 0; i < 4; i++) acc[mt][nt][i] = 0.f;

#pragma unroll
        for (int ks = 0; ks < 8; ks++) {
            const int k0 = ks * 8;
            uint32_t a[2][4];
#pragma unroll
            for (int mt = 0; mt < 2; mt++) {
                const int r0 = mbase + mt * 16 + lr;
                a[mt][0] = sAu[r0 * LDA + k0 + lc];
                a[mt][1] = sAu[(r0 + 8) * LDA + k0 + lc];
                a[mt][2] = sAu[r0 * LDA + k0 + lc + 4];
                a[mt][3] = sAu[(r0 + 8) * LDA + k0 + lc + 4];
            }
#pragma unroll
            for (int nt = 0; nt < 8; nt++) {
                const int n = nbase + nt * 8 + lr;
                uint32_t b0 = sBu[n * LDB + k0 + lc];
                uint32_t b1 = sBu[n * LDB + k0 + lc + 4];
                mma_tf32(acc[0][nt], a[0], b0, b1);
                mma_tf32(acc[1][nt], a[1], b0, b1);
            }
        }

        // ---- epilogue (R8-proven): dist = x2 + p2 - 2*xp, .cs v2 stores ----
        const long long m0 = (long long)t * M_TILE;
#pragma unroll
        for (int mt = 0; mt < 2; mt++) {
            const int r0 = mbase + mt * 16 + lr;
            const float xr0 = sx2[b * 128 + r0];
            const float xr1 = sx2[b * 128 + r0 + 8];
            float* o0 = out + (m0 + r0) * N_DIM;
            float* o1 = out + (m0 + r0 + 8) * N_DIM;
#pragma unroll
            for (int nt = 0; nt < 8; nt++) {
                const int col = nbase + nt * 8 + 2 * lc;
                const float p0 = sp2[col];
                const float p1 = sp2[col + 1];
                stg_cs_f2(o0 + col, xr0 + p0 - 2.f * acc[mt][nt][0],
                                    xr0 + p1 - 2.f * acc[mt][nt][1]);
                stg_cs_f2(o1 + col, xr1 + p0 - 2.f * acc[mt][nt][2],
                                    xr1 + p1 - 2.f * acc[mt][nt][3]);
            }
        }
        group_bar(wm + 1);   // group's stores of buf b done before restaging it
    }
}

// ---------------------------------------------------------------------------
extern "C" void kernel_launch(void* const* d_in, const int* in_sizes, int n_in,
                              void* d_out, int out_size) {
    const float* p0 = (const float*)d_in[0];
    const float* p1 = (const float*)d_in[1];
    // x is the big tensor (16777216 elems), omega is 16384.
    const float* x = p0, *omega = p1;
    if (n_in >= 2 && in_sizes[0] < in_sizes[1]) { x = p1; omega = p0; }

    (void)cudaFuncSetAttribute(dist_kernel,
                               cudaFuncAttributeMaxDynamicSharedMemorySize,
                               SMEM_BYTES);
    int grid = GRID_SMS < NTILES ? GRID_SMS : NTILES;
    dist_kernel<<<grid, NTHREADS, SMEM_BYTES>>>(x, omega, (float*)d_out);
}

// round 12
// speedup vs baseline: 1.2300x; 1.0166x over previous
#include <cuda_runtime.h>
#include <cstdint>

// dist[m,n] = ||x_m||^2 + ||w_n||^2 - 2<x_m,w_n>
// x [M=262144, K=64] fp32, omega [N=256, K=64] fp32, out [M,256,1] fp32.
// TF32 mma.sync, persistent CTAs (R8 skeleton, 92.2us). R10: per-tile CTA-wide
// __syncthreads replaced by per-row-group named barriers (4 warps, 128 thr):
// each group stages its own 32 A-rows -> 4 independent pipelines per CTA.
#define M_TILE 128
#define K_DIM  64
#define N_DIM  256
#define LDA    68      // padded float stride: bank=(4*row+col)%32 -> conflict-free
#define LDB    68
#define NTHREADS 512
#define NTILES 2048
#define GRID_SMS 148   // sm_100a B200

// dynamic smem layout (in floats)
#define F_SB   0                        // 256*68 = 17408
#define F_SA   17408                    // 2 bufs x 128*68 = 17408
#define F_P2   34816                    // 256
#define F_X2   35072                    // 2 x 128
#define SMEM_FLOATS 35328
#define SMEM_BYTES  (SMEM_FLOATS * 4)   // 141312

// ---------------------------------------------------------------------------
__device__ __forceinline__ uint32_t f2tf32(float f) {
    uint32_t u;
    asm("cvt.rna.tf32.f32 %0, %1;" : "=r"(u) : "f"(f));
    return u;
}

__device__ __forceinline__ void mma_tf32(float* d, const uint32_t* a,
                                         uint32_t b0, uint32_t b1) {
    asm volatile(
        "mma.sync.aligned.m16n8k8.row.col.f32.tf32.tf32.f32 "
        "{%0,%1,%2,%3}, {%4,%5,%6,%7}, {%8,%9}, {%0,%1,%2,%3};"
        : "+f"(d[0]), "+f"(d[1]), "+f"(d[2]), "+f"(d[3])
        : "r"(a[0]), "r"(a[1]), "r"(a[2]), "r"(a[3]), "r"(b0), "r"(b1));
}

__device__ __forceinline__ void stg_cs_f2(float* p, float x, float y) {
    asm volatile("st.global.cs.v2.f32 [%0], {%1, %2};"
                 :: "l"(p), "f"(x), "f"(y) : "memory");
}

__device__ __forceinline__ float red16(float s) {
    s += __shfl_xor_sync(0xffffffffu, s, 8);
    s += __shfl_xor_sync(0xffffffffu, s, 4);
    s += __shfl_xor_sync(0xffffffffu, s, 2);
    s += __shfl_xor_sync(0xffffffffu, s, 1);
    return s;
}

// named barrier over 128 threads (ids 1..4; 0 reserved for __syncthreads)
__device__ __forceinline__ void group_bar(int id) {
    asm volatile("bar.sync %0, %1;" :: "r"(id), "r"(128) : "memory");
}

// ---------------------------------------------------------------------------
// Persistent CTA: loops over [128 x 256] output tiles.
// 16 warps as 4(m) x 4(n). Row group g = warps 4g..4g+3 (tids 128g..128g+127)
// owns A rows [32g, 32g+32) and syncs only among itself per tile.
// ---------------------------------------------------------------------------
__global__ void __launch_bounds__(NTHREADS, 1)
dist_kernel(const float* __restrict__ x,
            const float* __restrict__ omega,
            float* __restrict__ out) {
    extern __shared__ float sm[];
    uint32_t* sBu = (uint32_t*)(sm + F_SB);
    float*    sp2 = sm + F_P2;
    float*    sx2 = sm + F_X2;          // [2][128]

    const int tid = threadIdx.x;

    // ---- stage B once (omega -> smem tf32) + p2 via shuffle reduce ----
    {
        const float4* gw = (const float4*)omega;
#pragma unroll
        for (int j = 0; j < 8; j++) {
            int i = tid + NTHREADS * j;          // 0..4095 (256 rows * 16 quads)
            int n = i >> 4, cc = i & 15;
            float4 v = __ldg(gw + i);
            float ss = red16(v.x * v.x + v.y * v.y + v.z * v.z + v.w * v.w);
            if ((tid & 15) == 0) sp2[n] = ss;
            uint4 t;
            t.x = f2tf32(v.x); t.y = f2tf32(v.y);
            t.z = f2tf32(v.z); t.w = f2tf32(v.w);
            *(uint4*)&sBu[n * LDB + cc * 4] = t;
        }
    }
    __syncthreads();   // B + p2 visible to all groups before independent loops

    // ---- warp tiling constants ----
    const int warp = tid >> 5;
    const int lane = tid & 31;
    const int wm = warp >> 2;           // row group g (== tid>>7)
    const int wn = warp & 3;
    const int mbase = wm * 32;
    const int nbase = wn * 64;
    const int lr = lane >> 2;
    const int lc = lane & 3;
    const int local = tid & 127;        // thread index within row group

    const int grid = gridDim.x;
    const int bid  = blockIdx.x;

    // ---- prefetch first tile (group's own 32 rows: 512 float4 / 128 thr) ----
    float4 v[4];
    {
        const float4* gx = (const float4*)(x + (long long)bid * M_TILE * K_DIM)
                         + mbase * (K_DIM / 4);   // group row base
#pragma unroll
        for (int j = 0; j < 4; j++) v[j] = __ldg(gx + local + 128 * j);
    }

    int k = 0;
    for (int t = bid; t < NTILES; t += grid, k++) {
        const int b = k & 1;
        uint32_t* sAu = (uint32_t*)(sm + F_SA) + b * (M_TILE * LDA);

        // ---- stage prefetched regs -> smem buf b (group rows only) ----
#pragma unroll
        for (int j = 0; j < 4; j++) {
            int idx = local + 128 * j;           // 0..511
            int row = mbase + (idx >> 4);        // group row
            int quad = idx & 15;
            float4 w = v[j];
            float ss = red16(w.x * w.x + w.y * w.y + w.z * w.z + w.w * w.w);
            if ((idx & 15) == 0) sx2[b * 128 + row] = ss;
            uint4 tv;
            tv.x = f2tf32(w.x); tv.y = f2tf32(w.y);
            tv.z = f2tf32(w.z); tv.w = f2tf32(w.w);
            *(uint4*)&sAu[row * LDA + quad * 4] = tv;
        }
        group_bar(wm + 1);

        // ---- issue prefetch LDGs for next tile (hidden under MMA) ----
        const int tn = t + grid;
        if (tn < NTILES) {
            const float4* gx = (const float4*)(x + (long long)tn * M_TILE * K_DIM)
                             + mbase * (K_DIM / 4);
#pragma unroll
            for (int j = 0; j < 4; j++) v[j] = __ldg(gx + local + 128 * j);
        }

        // ---- MMA: K in 8 steps of 8, operands from smem ----
        float acc[2][8][4];
#pragma unroll
        for (int mt = 0; mt < 2; mt++)
#pragma unroll
            for (int nt = 0; nt < 8; nt++)
#pragma unroll
                for (int i = 0; i < 4; i++) acc[mt][nt][i] = 0.f;

#pragma unroll
        for (int ks = 0; ks < 8; ks++) {
            const int k0 = ks * 8;
            uint32_t a[2][4];
#pragma unroll
            for (int mt = 0; mt < 2; mt++) {
                const int r0 = mbase + mt * 16 + lr;
                a[mt][0] = sAu[r0 * LDA + k0 + lc];
                a[mt][1] = sAu[(r0 + 8) * LDA + k0 + lc];
                a[mt][2] = sAu[r0 * LDA + k0 + lc + 4];
                a[mt][3] = sAu[(r0 + 8) * LDA + k0 + lc + 4];
            }
#pragma unroll
            for (int nt = 0; nt < 8; nt++) {
                const int n = nbase + nt * 8 + lr;
                uint32_t b0 = sBu[n * LDB + k0 + lc];
                uint32_t b1 = sBu[n * LDB + k0 + lc + 4];
                mma_tf32(acc[0][nt], a[0], b0, b1);
                mma_tf32(acc[1][nt], a[1], b0, b1);
            }
        }

        // ---- epilogue (R8-proven): dist = x2 + p2 - 2*xp, .cs v2 stores ----
        const long long m0 = (long long)t * M_TILE;
#pragma unroll
        for (int mt = 0; mt < 2; mt++) {
            const int r0 = mbase + mt * 16 + lr;
            const float xr0 = sx2[b * 128 + r0];
            const float xr1 = sx2[b * 128 + r0 + 8];
            float* o0 = out + (m0 + r0) * N_DIM;
            float* o1 = out + (m0 + r0 + 8) * N_DIM;
#pragma unroll
            for (int nt = 0; nt < 8; nt++) {
                const int col = nbase + nt * 8 + 2 * lc;
                const float p0 = sp2[col];
                const float p1 = sp2[col + 1];
                stg_cs_f2(o0 + col, xr0 + p0 - 2.f * acc[mt][nt][0],
                                    xr0 + p1 - 2.f * acc[mt][nt][1]);
                stg_cs_f2(o1 + col, xr1 + p0 - 2.f * acc[mt][nt][2],
                                    xr1 + p1 - 2.f * acc[mt][nt][3]);
            }
        }
        group_bar(wm + 1);   // group's stores of buf b done before restaging it
    }
}

// ---------------------------------------------------------------------------
extern "C" void kernel_launch(void* const* d_in, const int* in_sizes, int n_in,
                              void* d_out, int out_size) {
    const float* p0 = (const float*)d_in[0];
    const float* p1 = (const float*)d_in[1];
    // x is the big tensor (16777216 elems), omega is 16384.
    const float* x = p0, *omega = p1;
    if (n_in >= 2 && in_sizes[0] < in_sizes[1]) { x = p1; omega = p0; }

    (void)cudaFuncSetAttribute(dist_kernel,
                               cudaFuncAttributeMaxDynamicSharedMemorySize,
                               SMEM_BYTES);
    int grid = GRID_SMS < NTILES ? GRID_SMS : NTILES;
    dist_kernel<<<grid, NTHREADS, SMEM_BYTES>>>(x, omega, (float*)d_out);
}